// round 9
// baseline (speedup 1.0000x reference)
#include <cuda_runtime.h>

// Problem constants (VisualPromptEncoder_49074296324730)
#define BB    8
#define CC    256
#define HH    160
#define WW    160
#define NN    100    // boxes per image
#define NCLS  80     // classes
#define TROWS 32     // tile rows
#define NTILE 5      // HH / TROWS
#define PSTR  164    // padded row stride (mult of 4, conflict-free)
#define THR1  256    // 8 warps
#define NCOR  (4 * NN)

// ---------------------------------------------------------------------------
// One block per (b,c) plane. Register-prefetched tiles -> register row scan ->
// single STS; column scan keeps running SAT in a register and captures corner
// values inline (no SAT write-back, no harvest). Fused class-mean epilogue.
// ---------------------------------------------------------------------------
__global__ void __launch_bounds__(THR1, 4)
vpe_fused_kernel(const float* __restrict__ feat,
                 const float* __restrict__ boxes,
                 const int*   __restrict__ gtc,
                 const int*   __restrict__ neg_y,
                 const int*   __restrict__ neg_x,
                 const int*   __restrict__ img_h,
                 const int*   __restrict__ img_w,
                 float*       __restrict__ out)
{
    __shared__ float buf[TROWS * PSTR];   // scanned rows of current tile (21KB)
    __shared__ float cv[NCOR];            // corner SAT values
    __shared__ short cyv[NCOR];           // corner y (0..160)
    __shared__ short cxv[NCOR];           // corner x (0..160)
    __shared__ int   s_cls[NN];           // class per box (-1 invalid)
    __shared__ float s_pool[NN];          // pooled value per box
    __shared__ int   colcnt[WW];          // corners per column (x-1)
    __shared__ int   colstart[WW];        // exclusive prefix
    __shared__ int   colfill[WW];         // scatter cursor
    __shared__ short ccrow[NCOR];         // corner row (y-1), bucketed by col
    __shared__ short ccid[NCOR];          // corner id, bucketed by col

    const int blk  = blockIdx.x;          // b*CC + c
    const int b    = blk >> 8;
    const int c    = blk & 255;
    const int tid  = threadIdx.x;         // 0..255
    const int w    = tid >> 5;            // warp 0..7
    const int lane = tid & 31;

    const float4* plane4 = (const float4*)(feat + (size_t)blk * (HH * WW));

    // ---- prefetch registers: warp w holds rows w+8q (q=0..3) of a tile ----
    float4 pa[4], pb[4];

    #define LOADT(T)                                                          \
    {                                                                         \
        _Pragma("unroll")                                                     \
        for (int q = 0; q < 4; q++) {                                         \
            const int r = w + 8 * q;                                          \
            const float4* row4 = plane4 + (size_t)((T) * TROWS + r) * 40;     \
            pa[q] = row4[lane];                                               \
            pb[q] = (lane < 8) ? row4[32 + lane]                              \
                               : make_float4(0.f, 0.f, 0.f, 0.f);             \
        }                                                                     \
    }

    // issue tile-0 loads immediately; setup below covers the latency
    LOADT(0);

    // ---- setup: corners, classes, column buckets ----
    #pragma unroll
    for (int j = tid; j < NCOR; j += THR1) cv[j] = 0.f;
    if (tid < WW) { colcnt[tid] = 0; colfill[tid] = 0; }
    if (tid < NN) {
        const float sx = (float)WW / (float)img_w[0];
        const float sy = (float)HH / (float)img_h[0];
        const float* bx = boxes + ((size_t)b * NN + tid) * 4;
        const int x1 = (int)fminf(fmaxf(floorf(bx[0] * sx), 0.f), (float)WW);
        const int y1 = (int)fminf(fmaxf(floorf(bx[1] * sy), 0.f), (float)HH);
        const int x2 = (int)fminf(fmaxf(floorf(bx[2] * sx), 0.f), (float)WW);
        const int y2 = (int)fminf(fmaxf(floorf(bx[3] * sy), 0.f), (float)HH);
        cyv[tid          ] = (short)y2; cxv[tid          ] = (short)x2;  // s22
        cyv[tid +     NN ] = (short)y1; cxv[tid +     NN ] = (short)x2;  // s12
        cyv[tid + 2 * NN ] = (short)y2; cxv[tid + 2 * NN ] = (short)x1;  // s21
        cyv[tid + 3 * NN ] = (short)y1; cxv[tid + 3 * NN ] = (short)x1;  // s11
        s_cls[tid] = ((x2 > x1) && (y2 > y1)) ? gtc[b * NN + tid] : -1;
    }
    __syncthreads();

    // histogram corners by column (col = x-1)
    #pragma unroll
    for (int j = tid; j < NCOR; j += THR1) {
        const int y = cyv[j], x = cxv[j];
        if (y >= 1 && x >= 1) atomicAdd(&colcnt[x - 1], 1);
    }
    __syncthreads();

    // exclusive prefix over 160 columns (warp 0, lane owns 5 cols)
    if (w == 0) {
        int c0 = colcnt[5 * lane + 0], c1 = colcnt[5 * lane + 1];
        int c2 = colcnt[5 * lane + 2], c3 = colcnt[5 * lane + 3];
        int c4 = colcnt[5 * lane + 4];
        const int t = c0 + c1 + c2 + c3 + c4;
        int it = t;
        #pragma unroll
        for (int d = 1; d < 32; d <<= 1) {
            const int o = __shfl_up_sync(0xffffffffu, it, d);
            if (lane >= d) it += o;
        }
        int e = it - t;
        colstart[5 * lane + 0] = e; e += c0;
        colstart[5 * lane + 1] = e; e += c1;
        colstart[5 * lane + 2] = e; e += c2;
        colstart[5 * lane + 3] = e; e += c3;
        colstart[5 * lane + 4] = e;
    }
    __syncthreads();

    // scatter corner (row,id) into column buckets
    #pragma unroll
    for (int j = tid; j < NCOR; j += THR1) {
        const int y = cyv[j], x = cxv[j];
        if (y >= 1 && x >= 1) {
            const int pos = colstart[x - 1] + atomicAdd(&colfill[x - 1], 1);
            ccrow[pos] = (short)(y - 1);
            ccid[pos]  = (short)j;
        }
    }
    __syncthreads();

    // sort own column bucket by row; init capture cursor (same thread reads it)
    float run = 0.f;
    int   p = 0, pe = 0, nr = 0x7fff;
    if (tid < WW) {
        const int s0 = colstart[tid], e0 = s0 + colcnt[tid];
        for (int i = s0 + 1; i < e0; i++) {
            const short rw = ccrow[i], id = ccid[i];
            int k = i - 1;
            while (k >= s0 && ccrow[k] > rw) {
                ccrow[k + 1] = ccrow[k]; ccid[k + 1] = ccid[k]; k--;
            }
            ccrow[k + 1] = rw; ccid[k + 1] = id;
        }
        p  = s0;
        pe = e0;
        nr = (p < pe) ? (int)ccrow[p] : 0x7fff;
    }
    __syncthreads();   // protects bucket arrays from... (none write later) + aligns start

    // ---- main loop over tiles ----
    for (int t = 0; t < NTILE; t++) {
        // row scan from prefetched regs -> single STS per row segment
        #pragma unroll
        for (int q = 0; q < 4; q++) {
            const int r = w + 8 * q;
            float4 a  = pa[q];
            float4 bbv = pb[q];
            a.y += a.x; a.z += a.y; a.w += a.z;
            bbv.y += bbv.x; bbv.z += bbv.y; bbv.w += bbv.z;
            const float ta = a.w, tb = bbv.w;
            float ia = ta;
            #pragma unroll
            for (int d = 1; d < 32; d <<= 1) {
                const float o = __shfl_up_sync(0xffffffffu, ia, d);
                if (lane >= d) ia += o;
            }
            const float ea = ia - ta;
            const float T0 = __shfl_sync(0xffffffffu, ia, 31);
            float ib = tb;
            #pragma unroll
            for (int d = 1; d < 8; d <<= 1) {
                const float o = __shfl_up_sync(0xffffffffu, ib, d);
                if (lane >= d) ib += o;
            }
            const float eb = T0 + (ib - tb);
            float* dst = &buf[r * PSTR];
            *(float4*)&dst[4 * lane] =
                make_float4(a.x + ea, a.y + ea, a.z + ea, a.w + ea);
            if (lane < 8)
                *(float4*)&dst[128 + 4 * lane] =
                    make_float4(bbv.x + eb, bbv.y + eb, bbv.z + eb, bbv.w + eb);
        }

        // issue next tile's loads now; consumed after colscan + 2 barriers
        if (t < NTILE - 1) LOADT(t + 1);

        __syncthreads();

        // column scan with inline corner capture (threads 0..159)
        if (tid < WW) {
            #pragma unroll 8
            for (int ry = 0; ry < TROWS; ry++) {
                run += buf[ry * PSTR + tid];
                const int gr = t * TROWS + ry;
                while (gr == nr) {                    // rare
                    cv[ccid[p]] = run;
                    p++;
                    nr = (p < pe) ? (int)ccrow[p] : 0x7fff;
                }
            }
        }
        __syncthreads();
    }

    // ---- pooled value per box ----
    if (tid < NN) {
        const int x2 = cxv[tid], y2 = cyv[tid];
        const int x1 = cxv[tid + 2 * NN], y1 = cyv[tid + NN];
        float pv = 0.f;
        if (x2 > x1 && y2 > y1) {
            const float sum = cv[tid] - cv[tid + NN] - cv[tid + 2 * NN] + cv[tid + 3 * NN];
            int area = (x2 - x1) * (y2 - y1);
            if (area < 1) area = 1;
            pv = sum / (float)area;
        }
        s_pool[tid] = pv;
    }
    __syncthreads();

    // ---- per-class mean + negative fallback ----
    if (tid < NCLS) {
        const int cls = tid;
        float sum = 0.f;
        int   cnt = 0;
        #pragma unroll 4
        for (int n = 0; n < NN; n++) {
            if (s_cls[n] == cls) { sum += s_pool[n]; cnt++; }
        }
        float r;
        if (cnt > 0) {
            r = sum / (float)cnt;
        } else {
            const int ny = neg_y[b * NCLS + cls];
            const int nx = neg_x[b * NCLS + cls];
            r = feat[(((size_t)b * CC + c) * HH + ny) * WW + nx];
        }
        out[((size_t)b * NCLS + cls) * CC + c] = r;
    }
}

// ---------------------------------------------------------------------------
extern "C" void kernel_launch(void* const* d_in, const int* in_sizes, int n_in,
                              void* d_out, int out_size)
{
    const float* feat  = (const float*)d_in[0];   // [8,256,160,160] f32
    const float* boxes = (const float*)d_in[1];   // [8,100,4] f32
    const int*   gtc   = (const int*)d_in[2];     // [8,100] i32
    const int*   ngy   = (const int*)d_in[3];     // [8,80] i32
    const int*   ngx   = (const int*)d_in[4];     // [8,80] i32
    const int*   ih    = (const int*)d_in[5];     // scalar
    const int*   iw    = (const int*)d_in[6];     // scalar
    float*       out   = (float*)d_out;           // [8,80,256] f32

    vpe_fused_kernel<<<BB * CC, THR1>>>(feat, boxes, gtc, ngy, ngx, ih, iw, out);
}